// round 6
// baseline (speedup 1.0000x reference)
#include <cuda_runtime.h>
#include <cuda_bf16.h>
#include <math.h>
#include <stdint.h>

#define NB 4
#define NC 256
#define NT 4096
#define SHIFT 48.0f

typedef __nv_bfloat16 bf16;

__device__ bf16  g_xnhi[NB * NT * NC];
__device__ bf16  g_xnlo[NB * NT * NC];
__device__ bf16  g_qhi [NB * NT * NC];
__device__ bf16  g_qlo [NB * NT * NC];
__device__ bf16  g_khi [NB * NT * NC];
__device__ bf16  g_klo [NB * NT * NC];
__device__ bf16  g_vThi[NC * NB * NT];
__device__ bf16  g_vTlo[NC * NB * NT];
__device__ float g_s   [(size_t)NB * NT * NT];
__device__ float g_o   [NB * NT * NC];
__device__ float g_rowsum[NB * NT];
__device__ bf16  g_wqhi[NC * NC], g_wqlo[NC * NC];
__device__ bf16  g_wkhi[NC * NC], g_wklo[NC * NC];
__device__ bf16  g_wvhi[NC * NC], g_wvlo[NC * NC];

__device__ __forceinline__ uint32_t smem_u32(const void* p) {
    uint32_t a;
    asm("{ .reg .u64 t; cvta.to.shared.u64 t, %1; cvt.u32.u64 %0, t; }" : "=r"(a) : "l"(p));
    return a;
}
__device__ __forceinline__ void cp16(uint32_t s, const void* g) {
    asm volatile("cp.async.cg.shared.global [%0], [%1], 16;" :: "r"(s), "l"(g));
}
__device__ __forceinline__ void cp_commit() { asm volatile("cp.async.commit_group;" ::: "memory"); }
template <int N> __device__ __forceinline__ void cp_wait() {
    asm volatile("cp.async.wait_group %0;" :: "n"(N) : "memory");
}
__device__ __forceinline__ void ldm_x4(uint32_t* r, uint32_t addr) {
    asm volatile("ldmatrix.sync.aligned.m8n8.x4.shared.b16 {%0,%1,%2,%3}, [%4];"
                 : "=r"(r[0]), "=r"(r[1]), "=r"(r[2]), "=r"(r[3]) : "r"(addr));
}
__device__ __forceinline__ void mma16816(float* d, const uint32_t* a, const uint32_t* b) {
    asm volatile(
        "mma.sync.aligned.m16n8k16.row.col.f32.bf16.bf16.f32 "
        "{%0,%1,%2,%3}, {%4,%5,%6,%7}, {%8,%9}, {%0,%1,%2,%3};"
        : "+f"(d[0]), "+f"(d[1]), "+f"(d[2]), "+f"(d[3])
        : "r"(a[0]), "r"(a[1]), "r"(a[2]), "r"(a[3]), "r"(b[0]), "r"(b[1]));
}
__device__ __forceinline__ uint32_t swz(uint32_t off) { return off ^ ((off >> 3) & 0x70); }
__device__ __forceinline__ uint32_t pack2b(float a, float b) {
    return (uint32_t)__bfloat16_as_ushort(__float2bfloat16(a))
         | ((uint32_t)__bfloat16_as_ushort(__float2bfloat16(b)) << 16);
}

// ============================================================
// split-bf16 GEMM (3 products). EPI=1: bf16 pair out. EPI=0: fp32 out.
// EPI=2: fp32 out + rowsum of exp(v-SHIFT). CONV=1: A loaded as fp32 S,
// converted in smem to attn pair using rowsum/w1/w2.
// ============================================================
template <int EPI, int CONV>
__global__ void __launch_bounds__(256) mma_gemm(
    const bf16* __restrict__ Ahi, const bf16* __restrict__ Alo,
    const float* __restrict__ Asrc, long ldA, long strideA,
    const bf16* __restrict__ Bhi, const bf16* __restrict__ Blo, long ldB, long strideB,
    float* __restrict__ Cf, bf16* __restrict__ Chi, bf16* __restrict__ Clo,
    long ldC, long strideC, int K,
    float* __restrict__ rowsum, const float* __restrict__ w1, const float* __restrict__ w2)
{
    extern __shared__ char dyn[];
    __shared__ float sred[128];
    const uint32_t sbase = smem_u32(dyn);
    const int tid = threadIdx.x;
    const int wid = tid >> 5, lane = tid & 31;
    const int warpM = wid & 1, warpN = wid >> 1;

    constexpr uint32_t STAGE = CONV ? 49152u : 32768u;
    constexpr uint32_t AOFF  = CONV ? 16384u : 0u;      // pair-A slot in stage
    constexpr uint32_t BOFF  = CONV ? 32768u : 16384u;

    const int z = blockIdx.z;
    const long m0 = (long)blockIdx.y * 128;
    const long n0 = (long)blockIdx.x * 128;
    const bf16* pAh = Ahi + (size_t)z * strideA + (size_t)m0 * ldA;
    const bf16* pAl = Alo + (size_t)z * strideA + (size_t)m0 * ldA;
    const float* pS = Asrc + (size_t)z * strideA + (size_t)m0 * ldA;
    const bf16* pBh = Bhi + (size_t)z * strideB + (size_t)n0 * ldB;
    const bf16* pBl = Blo + (size_t)z * strideB + (size_t)n0 * ldB;

    float a2 = 0.f;
    if (CONV) {
        float e1 = __expf(w1[0]), e2 = __expf(w2[0]);
        a2 = e2 / (e1 + e2);
        if (tid < 128) sred[tid] = (e1 / (e1 + e2)) / rowsum[(size_t)z * NT + m0 + tid];
    } else if (EPI == 2) {
        if (tid < 128) sred[tid] = 0.f;
    }

    const int nk = K / 32;

    auto load_stage = [&](int st, int ks) {
        uint32_t base = sbase + st * STAGE;
#pragma unroll
        for (int i = 0; i < 4; i++) {
            int cid = tid + i * 256;
            int m = cid >> 3, c = cid & 7;
            uint32_t off = swz((uint32_t)(m * 128 + c * 16));
            int part = c >> 2, kc = c & 3;
            if (CONV) {
                cp16(base + off, pS + (size_t)m * ldA + ks * 32 + c * 4);
            } else {
                const bf16* ga = (part ? pAl : pAh) + (size_t)m * ldA + ks * 32 + kc * 8;
                cp16(base + AOFF + off, ga);
            }
            const bf16* gb = (part ? pBl : pBh) + (size_t)m * ldB + ks * 32 + kc * 8;
            cp16(base + BOFF + off, gb);
        }
    };

    float acc[4][4][4] = {};
    load_stage(0, 0);
    cp_commit();

    const int lr = lane & 7, lg = lane >> 3;

    for (int ks = 0; ks < nk; ks++) {
        int cur = ks & 1;
        if (ks + 1 < nk) { load_stage(cur ^ 1, ks + 1); cp_commit(); cp_wait<1>(); }
        else             { cp_wait<0>(); }
        __syncthreads();

        if (CONV) {
            char* stg = dyn + cur * STAGE;
            char* apair = stg + 16384;
#pragma unroll
            for (int j = 0; j < 4; j++) {
                int cid = tid + j * 256;
                int m = cid >> 3, c = cid & 7;
                float4 sv = *(float4*)(stg + swz((uint32_t)(m * 128 + c * 16)));
                float cr = sred[m];
                float p0 = cr * __expf(sv.x - SHIFT) + a2 * fmaxf(sv.x, 0.f) * fmaxf(sv.x, 0.f);
                float p1 = cr * __expf(sv.y - SHIFT) + a2 * fmaxf(sv.y, 0.f) * fmaxf(sv.y, 0.f);
                float p2 = cr * __expf(sv.z - SHIFT) + a2 * fmaxf(sv.z, 0.f) * fmaxf(sv.z, 0.f);
                float p3 = cr * __expf(sv.w - SHIFT) + a2 * fmaxf(sv.w, 0.f) * fmaxf(sv.w, 0.f);
                float h0 = __bfloat162float(__float2bfloat16(p0));
                float h1 = __bfloat162float(__float2bfloat16(p1));
                float h2 = __bfloat162float(__float2bfloat16(p2));
                float h3 = __bfloat162float(__float2bfloat16(p3));
                uint2 hv = make_uint2(pack2b(p0, p1), pack2b(p2, p3));
                uint2 lv = make_uint2(pack2b(p0 - h0, p1 - h1), pack2b(p2 - h2, p3 - h3));
                *(uint2*)(apair + swz((uint32_t)(m * 128 + c * 8)))      = hv;
                *(uint2*)(apair + swz((uint32_t)(m * 128 + 64 + c * 8))) = lv;
            }
            __syncthreads();
        }

        uint32_t aBase = sbase + cur * STAGE + AOFF;
        uint32_t bBase = sbase + cur * STAGE + BOFF;

#pragma unroll
        for (int kst = 0; kst < 2; kst++) {
            const uint32_t kb = kst * 32;
            uint32_t ah[4][4];
#pragma unroll
            for (int mf = 0; mf < 4; mf++) {
                uint32_t row = warpM * 64 + mf * 16 + lr + ((lg & 1) << 3);
                ldm_x4(ah[mf], aBase + swz(row * 128 + kb + ((lg >> 1) << 4)));
            }
            uint32_t bh[4][2];
#pragma unroll
            for (int p = 0; p < 2; p++) {
                uint32_t row = warpN * 32 + p * 16 + lr + ((lg >> 1) << 3);
                uint32_t t[4];
                ldm_x4(t, bBase + swz(row * 128 + kb + ((lg & 1) << 4)));
                bh[2*p][0] = t[0]; bh[2*p][1] = t[1];
                bh[2*p+1][0] = t[2]; bh[2*p+1][1] = t[3];
            }
#pragma unroll
            for (int mf = 0; mf < 4; mf++)
#pragma unroll
                for (int nf = 0; nf < 4; nf++)
                    mma16816(acc[mf][nf], ah[mf], bh[nf]);

            uint32_t bl[4][2];
#pragma unroll
            for (int p = 0; p < 2; p++) {
                uint32_t row = warpN * 32 + p * 16 + lr + ((lg >> 1) << 3);
                uint32_t t[4];
                ldm_x4(t, bBase + swz(row * 128 + 64 + kb + ((lg & 1) << 4)));
                bl[2*p][0] = t[0]; bl[2*p][1] = t[1];
                bl[2*p+1][0] = t[2]; bl[2*p+1][1] = t[3];
            }
#pragma unroll
            for (int mf = 0; mf < 4; mf++)
#pragma unroll
                for (int nf = 0; nf < 4; nf++)
                    mma16816(acc[mf][nf], ah[mf], bl[nf]);

#pragma unroll
            for (int mf = 0; mf < 4; mf++) {
                uint32_t al[4];
                uint32_t row = warpM * 64 + mf * 16 + lr + ((lg & 1) << 3);
                ldm_x4(al, aBase + swz(row * 128 + 64 + kb + ((lg >> 1) << 4)));
#pragma unroll
                for (int nf = 0; nf < 4; nf++)
                    mma16816(acc[mf][nf], al, bh[nf]);
            }
        }
        __syncthreads();
    }

    const int qr = lane >> 2, qc = (lane & 3) * 2;

    if (EPI == 2) {
#pragma unroll
        for (int mf = 0; mf < 4; mf++) {
            float s0 = 0.f, s1 = 0.f;
#pragma unroll
            for (int nf = 0; nf < 4; nf++) {
                s0 += __expf(acc[mf][nf][0] - SHIFT) + __expf(acc[mf][nf][1] - SHIFT);
                s1 += __expf(acc[mf][nf][2] - SHIFT) + __expf(acc[mf][nf][3] - SHIFT);
            }
            s0 += __shfl_xor_sync(0xffffffffu, s0, 1);
            s0 += __shfl_xor_sync(0xffffffffu, s0, 2);
            s1 += __shfl_xor_sync(0xffffffffu, s1, 1);
            s1 += __shfl_xor_sync(0xffffffffu, s1, 2);
            if ((lane & 3) == 0) {
                atomicAdd(&sred[warpM * 64 + mf * 16 + qr],     s0);
                atomicAdd(&sred[warpM * 64 + mf * 16 + qr + 8], s1);
            }
        }
        __syncthreads();
        if (tid < 128) atomicAdd(&rowsum[(size_t)z * NT + m0 + tid], sred[tid]);
    }

#pragma unroll
    for (int mf = 0; mf < 4; mf++) {
#pragma unroll
        for (int nf = 0; nf < 4; nf++) {
            long r0  = m0 + warpM * 64 + mf * 16 + qr;
            long col = n0 + warpN * 32 + nf * 8 + qc;
            if (EPI != 1) {
                float* d0 = Cf + (size_t)z * strideC + (size_t)r0 * ldC + col;
                *(float2*)d0             = make_float2(acc[mf][nf][0], acc[mf][nf][1]);
                *(float2*)(d0 + 8 * ldC) = make_float2(acc[mf][nf][2], acc[mf][nf][3]);
            } else {
#pragma unroll
                for (int h = 0; h < 2; h++) {
                    float v0 = acc[mf][nf][2*h], v1 = acc[mf][nf][2*h+1];
                    float h0 = __bfloat162float(__float2bfloat16(v0));
                    float h1 = __bfloat162float(__float2bfloat16(v1));
                    size_t idx = (size_t)z * strideC + (size_t)(r0 + h * 8) * ldC + col;
                    *(uint32_t*)(Chi + idx) = pack2b(v0, v1);
                    *(uint32_t*)(Clo + idx) = pack2b(v0 - h0, v1 - h1);
                }
            }
        }
    }
}

// ============================================================
__global__ void __launch_bounds__(256) ln_kernel(
    const float* __restrict__ x, const float* __restrict__ gamma,
    const float* __restrict__ beta, bf16* __restrict__ xnhi, bf16* __restrict__ xnlo)
{
    __shared__ float sx[32][NC + 1];
    __shared__ float psum[8][33], psq[8][33];
    __shared__ float smu[32], srs[32];
    int b = blockIdx.y, n0 = blockIdx.x * 32;
    const float* xb = x + (size_t)b * NC * NT;

    for (int i = threadIdx.x; i < NC * 32; i += 256) {
        int c = i >> 5, t = i & 31;
        sx[t][c] = xb[(size_t)c * NT + n0 + t];
    }
    __syncthreads();
    int t = threadIdx.x & 31, g = threadIdx.x >> 5;
    float s0 = 0.f, s1 = 0.f;
#pragma unroll
    for (int j = 0; j < 32; j++) { float v = sx[t][g * 32 + j]; s0 += v; s1 += v * v; }
    psum[g][t] = s0; psq[g][t] = s1;
    __syncthreads();
    if (threadIdx.x < 32) {
        float a = 0.f, bb = 0.f;
#pragma unroll
        for (int j = 0; j < 8; j++) { a += psum[j][threadIdx.x]; bb += psq[j][threadIdx.x]; }
        float mu = a * (1.0f / NC);
        smu[threadIdx.x] = mu;
        srs[threadIdx.x] = rsqrtf(bb * (1.0f / NC) - mu * mu + 1e-5f);
    }
    __syncthreads();
    size_t base = ((size_t)b * NT + n0) * NC;
    for (int i = threadIdx.x; i < NC * 32; i += 256) {
        int tok = i >> 8, c = i & 255;
        float r = (sx[tok][c] - smu[tok]) * srs[tok] * gamma[c] + beta[c];
        bf16 h = __float2bfloat16(r);
        xnhi[base + (size_t)tok * NC + c] = h;
        xnlo[base + (size_t)tok * NC + c] = __float2bfloat16(r - __bfloat162float(h));
    }
}

// prep: 3 weight transpose+splits + zero rowsum
__global__ void prep_kernel(
    const float* __restrict__ Wq, const float* __restrict__ Wk, const float* __restrict__ Wv,
    bf16* qh, bf16* ql, bf16* kh, bf16* kl, bf16* vh, bf16* vl, float* rowsum)
{
    int n = blockIdx.x, k = threadIdx.x;
    size_t src = (size_t)k * NC + n, dst = (size_t)n * NC + k;
    float v; bf16 h;
    v = Wq[src]; h = __float2bfloat16(v); qh[dst] = h; ql[dst] = __float2bfloat16(v - __bfloat162float(h));
    v = Wk[src]; h = __float2bfloat16(v); kh[dst] = h; kl[dst] = __float2bfloat16(v - __bfloat162float(h));
    v = Wv[src]; h = __float2bfloat16(v); vh[dst] = h; vl[dst] = __float2bfloat16(v - __bfloat162float(h));
    if (k < 64) rowsum[(size_t)n * 64 + k] = 0.f;
}

__global__ void out_kernel(const float* __restrict__ o, const bf16* __restrict__ xnhi,
                           const bf16* __restrict__ xnlo, float* __restrict__ out)
{
    __shared__ float tile[32][33];
    int b = blockIdx.z, n0 = blockIdx.x * 32, c0 = blockIdx.y * 32;
    for (int r = threadIdx.y; r < 32; r += 8) {
        size_t idx = ((size_t)b * NT + n0 + r) * NC + c0 + threadIdx.x;
        tile[r][threadIdx.x] = o[idx] + __bfloat162float(xnhi[idx]) + __bfloat162float(xnlo[idx]);
    }
    __syncthreads();
    for (int r = threadIdx.y; r < 32; r += 8)
        out[((size_t)b * NC + c0 + r) * NT + n0 + threadIdx.x] = tile[threadIdx.x][r];
}

// ============================================================
extern "C" void kernel_launch(void* const* d_in, const int* in_sizes, int n_in,
                              void* d_out, int out_size)
{
    const float* x     = (const float*)d_in[0];
    const float* gamma = (const float*)d_in[1];
    const float* beta  = (const float*)d_in[2];
    const float* Wq    = (const float*)d_in[3];
    const float* Wk    = (const float*)d_in[4];
    const float* Wv    = (const float*)d_in[5];
    const float* w1    = (const float*)d_in[6];
    const float* w2    = (const float*)d_in[7];
    float* out = (float*)d_out;

    bf16 *xnhi, *xnlo, *qhi, *qlo, *khi, *klo, *vThi, *vTlo;
    bf16 *wqhi, *wqlo, *wkhi, *wklo, *wvhi, *wvlo;
    float *s, *o, *rowsum;
    cudaGetSymbolAddress((void**)&xnhi, g_xnhi); cudaGetSymbolAddress((void**)&xnlo, g_xnlo);
    cudaGetSymbolAddress((void**)&qhi,  g_qhi);  cudaGetSymbolAddress((void**)&qlo,  g_qlo);
    cudaGetSymbolAddress((void**)&khi,  g_khi);  cudaGetSymbolAddress((void**)&klo,  g_klo);
    cudaGetSymbolAddress((void**)&vThi, g_vThi); cudaGetSymbolAddress((void**)&vTlo, g_vTlo);
    cudaGetSymbolAddress((void**)&wqhi, g_wqhi); cudaGetSymbolAddress((void**)&wqlo, g_wqlo);
    cudaGetSymbolAddress((void**)&wkhi, g_wkhi); cudaGetSymbolAddress((void**)&wklo, g_wklo);
    cudaGetSymbolAddress((void**)&wvhi, g_wvhi); cudaGetSymbolAddress((void**)&wvlo, g_wvlo);
    cudaGetSymbolAddress((void**)&s, g_s); cudaGetSymbolAddress((void**)&o, g_o);
    cudaGetSymbolAddress((void**)&rowsum, g_rowsum);

    cudaFuncSetAttribute((const void*)mma_gemm<1,0>, cudaFuncAttributeMaxDynamicSharedMemorySize, 65536);
    cudaFuncSetAttribute((const void*)mma_gemm<2,0>, cudaFuncAttributeMaxDynamicSharedMemorySize, 65536);
    cudaFuncSetAttribute((const void*)mma_gemm<0,1>, cudaFuncAttributeMaxDynamicSharedMemorySize, 98304);

    // 1) LayerNorm -> xn pair
    ln_kernel<<<dim3(NT / 32, NB), 256>>>(x, gamma, beta, xnhi, xnlo);
    // 2) weight splits + rowsum zero
    prep_kernel<<<NC, NC>>>(Wq, Wk, Wv, wqhi, wqlo, wkhi, wklo, wvhi, wvlo, rowsum);
    // 3-5) Q, K, V^T projections (pair out)
    mma_gemm<1,0><<<dim3(2, 128, 1), 256, 65536>>>(
        xnhi, xnlo, nullptr, NC, 0, wqhi, wqlo, NC, 0,
        nullptr, qhi, qlo, NC, 0, NC, nullptr, nullptr, nullptr);
    mma_gemm<1,0><<<dim3(2, 128, 1), 256, 65536>>>(
        xnhi, xnlo, nullptr, NC, 0, wkhi, wklo, NC, 0,
        nullptr, khi, klo, NC, 0, NC, nullptr, nullptr, nullptr);
    mma_gemm<1,0><<<dim3(128, 2, 1), 256, 65536>>>(
        wvhi, wvlo, nullptr, NC, 0, xnhi, xnlo, NC, 0,
        nullptr, vThi, vTlo, (long)NB * NT, 0, NC, nullptr, nullptr, nullptr);
    // 6) S = Q K^T (fp32 out + rowsum of exp(S-SHIFT))
    mma_gemm<2,0><<<dim3(32, 32, NB), 256, 65536>>>(
        qhi, qlo, nullptr, NC, (long)NT * NC, khi, klo, NC, (long)NT * NC,
        s, nullptr, nullptr, NT, (long)NT * NT, NC, rowsum, nullptr, nullptr);
    // 7) O = attn V, attn computed on the fly from S + rowsum
    mma_gemm<0,1><<<dim3(2, 32, NB), 256, 98304>>>(
        nullptr, nullptr, s, NT, (long)NT * NT, vThi, vTlo, (long)NB * NT, NT,
        o, nullptr, nullptr, NC, (long)NT * NC, NT, rowsum, w1, w2);
    // 8) transpose + residual
    out_kernel<<<dim3(NT / 32, NC / 32, NB), dim3(32, 8)>>>(o, xnhi, xnlo, out);
}

// round 7
// speedup vs baseline: 1.1185x; 1.1185x over previous
#include <cuda_runtime.h>
#include <cuda_bf16.h>
#include <math.h>
#include <stdint.h>

#define NB 4
#define NC 256
#define NT 4096

typedef __nv_bfloat16 bf16;

__device__ bf16  g_xnhi[NB * NT * NC];
__device__ bf16  g_xnlo[NB * NT * NC];
__device__ bf16  g_qhi [NB * NT * NC];
__device__ bf16  g_qlo [NB * NT * NC];
__device__ bf16  g_khi [NB * NT * NC];
__device__ bf16  g_klo [NB * NT * NC];
__device__ bf16  g_vThi[NC * NB * NT];
__device__ bf16  g_vTlo[NC * NB * NT];
__device__ float g_s   [(size_t)NB * NT * NT];
__device__ bf16  g_ahi [(size_t)NB * NT * NT];
__device__ bf16  g_alo [(size_t)NB * NT * NT];
__device__ float g_o   [NB * NT * NC];
__device__ bf16  g_wqhi[NC * NC], g_wqlo[NC * NC];
__device__ bf16  g_wkhi[NC * NC], g_wklo[NC * NC];
__device__ bf16  g_wvhi[NC * NC], g_wvlo[NC * NC];

__device__ __forceinline__ uint32_t smem_u32(const void* p) {
    uint32_t a;
    asm("{ .reg .u64 t; cvta.to.shared.u64 t, %1; cvt.u32.u64 %0, t; }" : "=r"(a) : "l"(p));
    return a;
}
__device__ __forceinline__ void cp16(uint32_t s, const void* g) {
    asm volatile("cp.async.cg.shared.global [%0], [%1], 16;" :: "r"(s), "l"(g));
}
__device__ __forceinline__ void cp_commit() { asm volatile("cp.async.commit_group;" ::: "memory"); }
template <int N> __device__ __forceinline__ void cp_wait() {
    asm volatile("cp.async.wait_group %0;" :: "n"(N) : "memory");
}
__device__ __forceinline__ void ldm_x4(uint32_t* r, uint32_t addr) {
    asm volatile("ldmatrix.sync.aligned.m8n8.x4.shared.b16 {%0,%1,%2,%3}, [%4];"
                 : "=r"(r[0]), "=r"(r[1]), "=r"(r[2]), "=r"(r[3]) : "r"(addr));
}
__device__ __forceinline__ void mma16816(float* d, const uint32_t* a, const uint32_t* b) {
    asm volatile(
        "mma.sync.aligned.m16n8k16.row.col.f32.bf16.bf16.f32 "
        "{%0,%1,%2,%3}, {%4,%5,%6,%7}, {%8,%9}, {%0,%1,%2,%3};"
        : "+f"(d[0]), "+f"(d[1]), "+f"(d[2]), "+f"(d[3])
        : "r"(a[0]), "r"(a[1]), "r"(a[2]), "r"(a[3]), "r"(b[0]), "r"(b[1]));
}
__device__ __forceinline__ uint32_t swz(uint32_t off) { return off ^ ((off >> 3) & 0x70); }
__device__ __forceinline__ uint32_t pack2b(float a, float b) {
    return (uint32_t)__bfloat16_as_ushort(__float2bfloat16(a))
         | ((uint32_t)__bfloat16_as_ushort(__float2bfloat16(b)) << 16);
}

// ============================================================
// split-bf16 GEMM (3 products): D = Ahi*Bhi^T + Ahi*Blo^T + Alo*Bhi^T
// BM=BN=128, BK=32, 256 thr (8 warps, 2x4), warp tile 64x32.
// __launch_bounds__(256,2): cap regs at 128 -> 2 CTAs/SM.
// EPI=0: fp32 out. EPI=1: bf16 hi/lo pair out.
// ============================================================
template <int EPI>
__global__ void __launch_bounds__(256, 2) mma_gemm(
    const bf16* __restrict__ Ahi, const bf16* __restrict__ Alo, long ldA, long strideA,
    const bf16* __restrict__ Bhi, const bf16* __restrict__ Blo, long ldB, long strideB,
    float* __restrict__ Cf, bf16* __restrict__ Chi, bf16* __restrict__ Clo,
    long ldC, long strideC, int K)
{
    extern __shared__ char dyn[];
    const uint32_t sbase = smem_u32(dyn);
    const int tid = threadIdx.x;
    const int wid = tid >> 5, lane = tid & 31;
    const int warpM = wid & 1, warpN = wid >> 1;

    const int z = blockIdx.z;
    const long m0 = (long)blockIdx.y * 128;
    const long n0 = (long)blockIdx.x * 128;
    const bf16* pAh = Ahi + (size_t)z * strideA + (size_t)m0 * ldA;
    const bf16* pAl = Alo + (size_t)z * strideA + (size_t)m0 * ldA;
    const bf16* pBh = Bhi + (size_t)z * strideB + (size_t)n0 * ldB;
    const bf16* pBl = Blo + (size_t)z * strideB + (size_t)n0 * ldB;

    const int nk = K / 32;
    const uint32_t STAGE = 32768;

    auto load_stage = [&](int st, int ks) {
        uint32_t base = sbase + st * STAGE;
#pragma unroll
        for (int i = 0; i < 4; i++) {
            int cid = tid + i * 256;
            int m = cid >> 3, c = cid & 7;
            int part = c >> 2, kc = c & 3;
            uint32_t off = swz((uint32_t)(m * 128 + c * 16));
            const bf16* ga = (part ? pAl : pAh) + (size_t)m * ldA + ks * 32 + kc * 8;
            const bf16* gb = (part ? pBl : pBh) + (size_t)m * ldB + ks * 32 + kc * 8;
            cp16(base + off, ga);
            cp16(base + 16384u + off, gb);
        }
    };

    float acc[4][4][4] = {};
    load_stage(0, 0);
    cp_commit();

    const int lr = lane & 7, lg = lane >> 3;

    for (int ks = 0; ks < nk; ks++) {
        int cur = ks & 1;
        if (ks + 1 < nk) { load_stage(cur ^ 1, ks + 1); cp_commit(); cp_wait<1>(); }
        else             { cp_wait<0>(); }
        __syncthreads();

        uint32_t aBase = sbase + cur * STAGE;
        uint32_t bBase = aBase + 16384u;

#pragma unroll
        for (int kst = 0; kst < 2; kst++) {
            const uint32_t kb = kst * 32;
            uint32_t ah[4][4];
#pragma unroll
            for (int mf = 0; mf < 4; mf++) {
                uint32_t row = warpM * 64 + mf * 16 + lr + ((lg & 1) << 3);
                ldm_x4(ah[mf], aBase + swz(row * 128 + kb + ((lg >> 1) << 4)));
            }
            uint32_t bh[4][2];
#pragma unroll
            for (int p = 0; p < 2; p++) {
                uint32_t row = warpN * 32 + p * 16 + lr + ((lg >> 1) << 3);
                uint32_t t[4];
                ldm_x4(t, bBase + swz(row * 128 + kb + ((lg & 1) << 4)));
                bh[2*p][0] = t[0]; bh[2*p][1] = t[1];
                bh[2*p+1][0] = t[2]; bh[2*p+1][1] = t[3];
            }
#pragma unroll
            for (int mf = 0; mf < 4; mf++)
#pragma unroll
                for (int nf = 0; nf < 4; nf++)
                    mma16816(acc[mf][nf], ah[mf], bh[nf]);

            uint32_t bl[4][2];
#pragma unroll
            for (int p = 0; p < 2; p++) {
                uint32_t row = warpN * 32 + p * 16 + lr + ((lg >> 1) << 3);
                uint32_t t[4];
                ldm_x4(t, bBase + swz(row * 128 + 64 + kb + ((lg & 1) << 4)));
                bl[2*p][0] = t[0]; bl[2*p][1] = t[1];
                bl[2*p+1][0] = t[2]; bl[2*p+1][1] = t[3];
            }
#pragma unroll
            for (int mf = 0; mf < 4; mf++)
#pragma unroll
                for (int nf = 0; nf < 4; nf++)
                    mma16816(acc[mf][nf], ah[mf], bl[nf]);

#pragma unroll
            for (int mf = 0; mf < 4; mf++) {
                uint32_t al[4];
                uint32_t row = warpM * 64 + mf * 16 + lr + ((lg & 1) << 3);
                ldm_x4(al, aBase + swz(row * 128 + 64 + kb + ((lg >> 1) << 4)));
#pragma unroll
                for (int nf = 0; nf < 4; nf++)
                    mma16816(acc[mf][nf], al, bh[nf]);
            }
        }
        __syncthreads();
    }

    const int qr = lane >> 2, qc = (lane & 3) * 2;
#pragma unroll
    for (int mf = 0; mf < 4; mf++) {
#pragma unroll
        for (int nf = 0; nf < 4; nf++) {
            long r0  = m0 + warpM * 64 + mf * 16 + qr;
            long col = n0 + warpN * 32 + nf * 8 + qc;
            if (EPI == 0) {
                float* d0 = Cf + (size_t)z * strideC + (size_t)r0 * ldC + col;
                *(float2*)d0             = make_float2(acc[mf][nf][0], acc[mf][nf][1]);
                *(float2*)(d0 + 8 * ldC) = make_float2(acc[mf][nf][2], acc[mf][nf][3]);
            } else {
#pragma unroll
                for (int h = 0; h < 2; h++) {
                    float v0 = acc[mf][nf][2*h], v1 = acc[mf][nf][2*h+1];
                    float h0 = __bfloat162float(__float2bfloat16(v0));
                    float h1 = __bfloat162float(__float2bfloat16(v1));
                    size_t idx = (size_t)z * strideC + (size_t)(r0 + h * 8) * ldC + col;
                    *(uint32_t*)(Chi + idx) = pack2b(v0, v1);
                    *(uint32_t*)(Clo + idx) = pack2b(v0 - h0, v1 - h1);
                }
            }
        }
    }
}

// ============================================================
__global__ void __launch_bounds__(256) ln_kernel(
    const float* __restrict__ x, const float* __restrict__ gamma,
    const float* __restrict__ beta, bf16* __restrict__ xnhi, bf16* __restrict__ xnlo)
{
    __shared__ float sx[32][NC + 1];
    __shared__ float psum[8][33], psq[8][33];
    __shared__ float smu[32], srs[32];
    int b = blockIdx.y, n0 = blockIdx.x * 32;
    const float* xb = x + (size_t)b * NC * NT;

    for (int i = threadIdx.x; i < NC * 32; i += 256) {
        int c = i >> 5, t = i & 31;
        sx[t][c] = xb[(size_t)c * NT + n0 + t];
    }
    __syncthreads();
    int t = threadIdx.x & 31, g = threadIdx.x >> 5;
    float s0 = 0.f, s1 = 0.f;
#pragma unroll
    for (int j = 0; j < 32; j++) { float v = sx[t][g * 32 + j]; s0 += v; s1 += v * v; }
    psum[g][t] = s0; psq[g][t] = s1;
    __syncthreads();
    if (threadIdx.x < 32) {
        float a = 0.f, bb = 0.f;
#pragma unroll
        for (int j = 0; j < 8; j++) { a += psum[j][threadIdx.x]; bb += psq[j][threadIdx.x]; }
        float mu = a * (1.0f / NC);
        smu[threadIdx.x] = mu;
        srs[threadIdx.x] = rsqrtf(bb * (1.0f / NC) - mu * mu + 1e-5f);
    }
    __syncthreads();
    size_t base = ((size_t)b * NT + n0) * NC;
    for (int i = threadIdx.x; i < NC * 32; i += 256) {
        int tok = i >> 8, c = i & 255;
        float r = (sx[tok][c] - smu[tok]) * srs[tok] * gamma[c] + beta[c];
        bf16 h = __float2bfloat16(r);
        xnhi[base + (size_t)tok * NC + c] = h;
        xnlo[base + (size_t)tok * NC + c] = __float2bfloat16(r - __bfloat162float(h));
    }
}

__global__ void prep_kernel(
    const float* __restrict__ Wq, const float* __restrict__ Wk, const float* __restrict__ Wv,
    bf16* qh, bf16* ql, bf16* kh, bf16* kl, bf16* vh, bf16* vl)
{
    int n = blockIdx.x, k = threadIdx.x;
    size_t src = (size_t)k * NC + n, dst = (size_t)n * NC + k;
    float v; bf16 h;
    v = Wq[src]; h = __float2bfloat16(v); qh[dst] = h; ql[dst] = __float2bfloat16(v - __bfloat162float(h));
    v = Wk[src]; h = __float2bfloat16(v); kh[dst] = h; kl[dst] = __float2bfloat16(v - __bfloat162float(h));
    v = Wv[src]; h = __float2bfloat16(v); vh[dst] = h; vl[dst] = __float2bfloat16(v - __bfloat162float(h));
}

// mix: S row -> a1*softmax + a2*relu^2, bf16 pair out
__global__ void __launch_bounds__(256) mix_kernel(
    const float* __restrict__ w1, const float* __restrict__ w2,
    const float* __restrict__ S, bf16* __restrict__ ahi, bf16* __restrict__ alo)
{
    size_t ro = ((size_t)blockIdx.y * NT + blockIdx.x) * NT;
    const float4* row4 = (const float4*)(S + ro);
    int tid = threadIdx.x;
    __shared__ float sred[8];

    float4 v[4];
    float mx = -1e30f;
#pragma unroll
    for (int g = 0; g < 4; g++) {
        v[g] = row4[g * 256 + tid];
        mx = fmaxf(mx, fmaxf(fmaxf(v[g].x, v[g].y), fmaxf(v[g].z, v[g].w)));
    }
#pragma unroll
    for (int o = 16; o; o >>= 1) mx = fmaxf(mx, __shfl_xor_sync(0xffffffffu, mx, o));
    if ((tid & 31) == 0) sred[tid >> 5] = mx;
    __syncthreads();
    mx = sred[0];
#pragma unroll
    for (int i = 1; i < 8; i++) mx = fmaxf(mx, sred[i]);
    __syncthreads();

    float4 e[4];
    float sum = 0.f;
#pragma unroll
    for (int g = 0; g < 4; g++) {
        e[g].x = __expf(v[g].x - mx); e[g].y = __expf(v[g].y - mx);
        e[g].z = __expf(v[g].z - mx); e[g].w = __expf(v[g].w - mx);
        sum += e[g].x + e[g].y + e[g].z + e[g].w;
    }
#pragma unroll
    for (int o = 16; o; o >>= 1) sum += __shfl_xor_sync(0xffffffffu, sum, o);
    if ((tid & 31) == 0) sred[tid >> 5] = sum;
    __syncthreads();
    sum = 0.f;
#pragma unroll
    for (int i = 0; i < 8; i++) sum += sred[i];

    float e1 = __expf(w1[0]), e2 = __expf(w2[0]);
    float a1 = e1 / (e1 + e2), a2 = e2 / (e1 + e2);
    float inv = a1 / sum;

    uint2* oh = (uint2*)(ahi + ro);
    uint2* ol = (uint2*)(alo + ro);
#pragma unroll
    for (int g = 0; g < 4; g++) {
        float p0 = e[g].x * inv + a2 * fmaxf(v[g].x, 0.f) * fmaxf(v[g].x, 0.f);
        float p1 = e[g].y * inv + a2 * fmaxf(v[g].y, 0.f) * fmaxf(v[g].y, 0.f);
        float p2 = e[g].z * inv + a2 * fmaxf(v[g].z, 0.f) * fmaxf(v[g].z, 0.f);
        float p3 = e[g].w * inv + a2 * fmaxf(v[g].w, 0.f) * fmaxf(v[g].w, 0.f);
        float h0 = __bfloat162float(__float2bfloat16(p0));
        float h1 = __bfloat162float(__float2bfloat16(p1));
        float h2 = __bfloat162float(__float2bfloat16(p2));
        float h3 = __bfloat162float(__float2bfloat16(p3));
        oh[g * 256 + tid] = make_uint2(pack2b(p0, p1), pack2b(p2, p3));
        ol[g * 256 + tid] = make_uint2(pack2b(p0 - h0, p1 - h1), pack2b(p2 - h2, p3 - h3));
    }
}

__global__ void out_kernel(const float* __restrict__ o, const bf16* __restrict__ xnhi,
                           const bf16* __restrict__ xnlo, float* __restrict__ out)
{
    __shared__ float tile[32][33];
    int b = blockIdx.z, n0 = blockIdx.x * 32, c0 = blockIdx.y * 32;
    for (int r = threadIdx.y; r < 32; r += 8) {
        size_t idx = ((size_t)b * NT + n0 + r) * NC + c0 + threadIdx.x;
        tile[r][threadIdx.x] = o[idx] + __bfloat162float(xnhi[idx]) + __bfloat162float(xnlo[idx]);
    }
    __syncthreads();
    for (int r = threadIdx.y; r < 32; r += 8)
        out[((size_t)b * NC + c0 + r) * NT + n0 + threadIdx.x] = tile[threadIdx.x][r];
}

// ============================================================
extern "C" void kernel_launch(void* const* d_in, const int* in_sizes, int n_in,
                              void* d_out, int out_size)
{
    const float* x     = (const float*)d_in[0];
    const float* gamma = (const float*)d_in[1];
    const float* beta  = (const float*)d_in[2];
    const float* Wq    = (const float*)d_in[3];
    const float* Wk    = (const float*)d_in[4];
    const float* Wv    = (const float*)d_in[5];
    const float* w1    = (const float*)d_in[6];
    const float* w2    = (const float*)d_in[7];
    float* out = (float*)d_out;

    bf16 *xnhi, *xnlo, *qhi, *qlo, *khi, *klo, *vThi, *vTlo;
    bf16 *wqhi, *wqlo, *wkhi, *wklo, *wvhi, *wvlo, *ahi, *alo;
    float *s, *o;
    cudaGetSymbolAddress((void**)&xnhi, g_xnhi); cudaGetSymbolAddress((void**)&xnlo, g_xnlo);
    cudaGetSymbolAddress((void**)&qhi,  g_qhi);  cudaGetSymbolAddress((void**)&qlo,  g_qlo);
    cudaGetSymbolAddress((void**)&khi,  g_khi);  cudaGetSymbolAddress((void**)&klo,  g_klo);
    cudaGetSymbolAddress((void**)&vThi, g_vThi); cudaGetSymbolAddress((void**)&vTlo, g_vTlo);
    cudaGetSymbolAddress((void**)&wqhi, g_wqhi); cudaGetSymbolAddress((void**)&wqlo, g_wqlo);
    cudaGetSymbolAddress((void**)&wkhi, g_wkhi); cudaGetSymbolAddress((void**)&wklo, g_wklo);
    cudaGetSymbolAddress((void**)&wvhi, g_wvhi); cudaGetSymbolAddress((void**)&wvlo, g_wvlo);
    cudaGetSymbolAddress((void**)&ahi,  g_ahi);  cudaGetSymbolAddress((void**)&alo,  g_alo);
    cudaGetSymbolAddress((void**)&s, g_s); cudaGetSymbolAddress((void**)&o, g_o);

    cudaFuncSetAttribute((const void*)mma_gemm<0>, cudaFuncAttributeMaxDynamicSharedMemorySize, 65536);
    cudaFuncSetAttribute((const void*)mma_gemm<1>, cudaFuncAttributeMaxDynamicSharedMemorySize, 65536);

    // 1) LayerNorm -> xn pair
    ln_kernel<<<dim3(NT / 32, NB), 256>>>(x, gamma, beta, xnhi, xnlo);
    // 2) weight transpose+split (one launch)
    prep_kernel<<<NC, NC>>>(Wq, Wk, Wv, wqhi, wqlo, wkhi, wklo, wvhi, wvlo);
    // 3-5) Q, K, V^T projections (pair out)
    mma_gemm<1><<<dim3(2, 128, 1), 256, 65536>>>(
        xnhi, xnlo, NC, 0, wqhi, wqlo, NC, 0, nullptr, qhi, qlo, NC, 0, NC);
    mma_gemm<1><<<dim3(2, 128, 1), 256, 65536>>>(
        xnhi, xnlo, NC, 0, wkhi, wklo, NC, 0, nullptr, khi, klo, NC, 0, NC);
    mma_gemm<1><<<dim3(128, 2, 1), 256, 65536>>>(
        wvhi, wvlo, NC, 0, xnhi, xnlo, NC, 0, nullptr, vThi, vTlo, (long)NB * NT, 0, NC);
    // 6) S = Q K^T per batch (fp32)
    mma_gemm<0><<<dim3(32, 32, NB), 256, 65536>>>(
        qhi, qlo, NC, (long)NT * NC, khi, klo, NC, (long)NT * NC,
        s, nullptr, nullptr, NT, (long)NT * NT, NC);
    // 7) attn = a1*softmax(S)+a2*relu(S)^2 -> pair
    mix_kernel<<<dim3(NT, NB), 256>>>(w1, w2, s, ahi, alo);
    // 8) O = attn @ V per batch
    mma_gemm<0><<<dim3(2, 32, NB), 256, 65536>>>(
        ahi, alo, NT, (long)NT * NT, vThi, vTlo, (long)NB * NT, NT,
        o, nullptr, nullptr, NC, (long)NT * NC, NT);
    // 9) transpose + residual
    out_kernel<<<dim3(NT / 32, NC / 32, NB), dim3(32, 8)>>>(o, xnhi, xnlo, out);
}